// round 12
// baseline (speedup 1.0000x reference)
#include <cuda_runtime.h>
#include <cuda_fp16.h>
#include <math.h>

#define HID   64
#define NPT   128
#define LBF   (-5.0f)
#define BPB   8      // batches per block

__device__ __forceinline__ unsigned pack_h2(float lo, float hi) {
    const __half2 h = __floats2half2_rn(lo, hi);
    return *reinterpret_cast<const unsigned*>(&h);
}

// fp16-accumulator mma: C/D are two f16x2 regs
__device__ __forceinline__ void mma_f16acc(unsigned c[2],
                                           unsigned a0, unsigned a1, unsigned a2, unsigned a3,
                                           unsigned b0, unsigned b1) {
    asm volatile(
        "mma.sync.aligned.m16n8k16.row.col.f16.f16.f16.f16 "
        "{%0,%1}, {%2,%3,%4,%5}, {%6,%7}, {%0,%1};\n"
        : "+r"(c[0]), "+r"(c[1])
        : "r"(a0), "r"(a1), "r"(a2), "r"(a3), "r"(b0), "r"(b1));
}

__device__ __forceinline__ __half2 lrelu2(__half2 h, __half2 c001) {
    return __hmax2(h, __hmul2(h, c001));
}

__global__ __launch_bounds__(128, 8)
void mono_mlp_h2f_kernel(const float* __restrict__ z,  const float* __restrict__ u,
                         const float* __restrict__ w01, const float* __restrict__ b01,
                         const float* __restrict__ w02, const float* __restrict__ b02,
                         const float* __restrict__ w03, const float* __restrict__ b03,
                         const float* __restrict__ w11, const float* __restrict__ b11,
                         const float* __restrict__ w12, const float* __restrict__ b12,
                         const float* __restrict__ w13, const float* __restrict__ b13,
                         const float* __restrict__ bias, float* __restrict__ out, int B)
{
    // layer-1 packed: w1b1h[d][4*kt + tig]
    __shared__ uint4  w1b1h[2][16];
    __shared__ float  b3s[2];
    __shared__ unsigned xs2h[BPB][NPT];   // x broadcast as half2, all batches of one d
    __shared__ float  dszs[BPB];
    // per-point partial sums: sredf[nhalf][bi][slot] = (s at p0, s at p1)
    //   slot = 8*pt_tile + gid, p0 = 16*pt_tile + gid, p1 = p0 + 8
    __shared__ float2 sredf[2][BPB][64];  // 8 KB
    __shared__ float  redw[BPB];
    __shared__ float  hzacc[BPB];

    const int tid = threadIdx.x;

    if (tid < 32) {
        const int d  = tid >> 4;
        const int j  = tid & 15;           // 4*kt + tig
        const int k0 = 16 * (j >> 2) + 2 * (j & 3);
        const float* w1 = d ? w11 : w01;
        const float* bb = d ? b11 : b01;
        w1b1h[d][j] = make_uint4(pack_h2(w1[k0],     w1[k0 + 1]),
                                 pack_h2(bb[k0],     bb[k0 + 1]),
                                 pack_h2(w1[k0 + 8], w1[k0 + 9]),
                                 pack_h2(bb[k0 + 8], bb[k0 + 9]));
    }
    if (tid == 0) { b3s[0] = b03[0]; b3s[1] = b13[0]; }
    if (tid < BPB) hzacc[tid] = bias[0];

    const int warp  = tid >> 5;
    const int lane  = tid & 31;
    const int gid   = lane >> 2;       // row within m16 group
    const int tig   = lane & 3;        // k / col selector
    const int nhalf = warp & 1;        // n-cols [32*nhalf, +32)
    const int pgrp  = warp >> 1;       // points [64*pgrp, +64)
    const int pbase = 64 * pgrp;
    const int b0    = blockIdx.x * BPB;
    const __half2 c001 = __float2half2_rn(0.01f);
    __syncthreads();

    #pragma unroll 1
    for (int d = 0; d < 2; d++) {
        // ---- persistent per-d registers, straight from gmem ----
        // B fragments (W2)
        uint2 bfr[4][4];
        {
            const float* w2 = d ? w12 : w02;
            #pragma unroll
            for (int kt = 0; kt < 4; kt++) {
                const int k0 = 16 * kt + 2 * tig;
                #pragma unroll
                for (int ntl = 0; ntl < 4; ntl++) {
                    const int n = 8 * (4 * nhalf + ntl) + gid;
                    bfr[kt][ntl] = make_uint2(
                        pack_h2(w2[n * 64 + k0],     w2[n * 64 + k0 + 1]),
                        pack_h2(w2[n * 64 + k0 + 8], w2[n * 64 + k0 + 9]));
                }
            }
        }
        // epilogue weights (w3 pair, b2 pair) for this lane's 4 ntl columns
        uint2 wb[4];
        {
            const float* w3 = d ? w13 : w03;
            const float* b2 = d ? b12 : b02;
            #pragma unroll
            for (int ntl = 0; ntl < 4; ntl++) {
                const int j = 2 * (16 * nhalf + 4 * ntl + tig);
                wb[ntl] = make_uint2(pack_h2(w3[j], w3[j + 1]),
                                     pack_h2(b2[j], b2[j + 1]));
            }
        }
        const float b3v = b3s[d];

        // ---- stage 0: layer-0 inputs for all 8 batches of this d ----
        #pragma unroll 1
        for (int it = 0; it < BPB; it++) {
            const int bb_ = b0 + it;
            const float zc  = fmaxf(z[bb_ * 2 + d], LBF);
            const float dsz = (zc - LBF) * (1.0f / (float)(NPT - 1));
            const float uv  = (tid < NPT - 1) ? u[(bb_ * 2 + d) * (NPT - 1) + tid] : 0.0f;
            const float x   = fmaf(dsz, (float)tid + uv, LBF);
            xs2h[it][tid] = pack_h2(x, x);
            if (tid == 0) dszs[it] = dsz;
        }
        __syncthreads();   // (1) xs2h/dszs ready; prev-d sredf fully consumed

        // ---- GEMM over 8 batches: no block barriers inside ----
        #pragma unroll 1
        for (int bi = 0; bi < BPB; bi++) {
            #pragma unroll
            for (int rnd = 0; rnd < 4; rnd++) {
                const int pr = pbase + 16 * rnd;
                const int p0 = pr + gid;
                const int p1 = p0 + 8;
                const __half2 x0h = *reinterpret_cast<const __half2*>(&xs2h[bi][p0]);
                const __half2 x1h = *reinterpret_cast<const __half2*>(&xs2h[bi][p1]);

                // acc init: C = b2 (register, no LDS on the mma chain head)
                unsigned acc[4][2];
                #pragma unroll
                for (int ntl = 0; ntl < 4; ntl++) {
                    acc[ntl][0] = wb[ntl].y;
                    acc[ntl][1] = wb[ntl].y;
                }

                #pragma unroll
                for (int kt = 0; kt < 4; kt++) {
                    const uint4 wp = w1b1h[d][4 * kt + tig];
                    const __half2 wlo = *reinterpret_cast<const __half2*>(&wp.x);
                    const __half2 blo = *reinterpret_cast<const __half2*>(&wp.y);
                    const __half2 whi = *reinterpret_cast<const __half2*>(&wp.z);
                    const __half2 bhi = *reinterpret_cast<const __half2*>(&wp.w);

                    const __half2 h0lo = lrelu2(__hfma2(x0h, wlo, blo), c001);
                    const __half2 h1lo = lrelu2(__hfma2(x1h, wlo, blo), c001);
                    const __half2 h0hi = lrelu2(__hfma2(x0h, whi, bhi), c001);
                    const __half2 h1hi = lrelu2(__hfma2(x1h, whi, bhi), c001);
                    const unsigned a0 = *reinterpret_cast<const unsigned*>(&h0lo);
                    const unsigned a1 = *reinterpret_cast<const unsigned*>(&h1lo);
                    const unsigned a2 = *reinterpret_cast<const unsigned*>(&h0hi);
                    const unsigned a3 = *reinterpret_cast<const unsigned*>(&h1hi);

                    mma_f16acc(acc[0], a0, a1, a2, a3, bfr[kt][0].x, bfr[kt][0].y);
                    mma_f16acc(acc[1], a0, a1, a2, a3, bfr[kt][1].x, bfr[kt][1].y);
                    mma_f16acc(acc[2], a0, a1, a2, a3, bfr[kt][2].x, bfr[kt][2].y);
                    mma_f16acc(acc[3], a0, a1, a2, a3, bfr[kt][3].x, bfr[kt][3].y);
                }

                // ---- epilogue: fp16 dot (b2 already in acc), fp32 parallel folds ----
                __half2 s0h = __float2half2_rn(0.0f);
                __half2 s1h = s0h;
                #pragma unroll
                for (int ntl = 0; ntl < 4; ntl++) {
                    const __half2 w3p = *reinterpret_cast<const __half2*>(&wb[ntl].x);
                    const __half2 p0p = *reinterpret_cast<const __half2*>(&acc[ntl][0]);
                    const __half2 p1p = *reinterpret_cast<const __half2*>(&acc[ntl][1]);
                    s0h = __hfma2(lrelu2(p0p, c001), w3p, s0h);
                    s1h = __hfma2(lrelu2(p1p, c001), w3p, s1h);
                }
                float s0 = __low2float(s0h) + __high2float(s0h);
                float s1 = __low2float(s1h) + __high2float(s1h);
                s0 += __shfl_xor_sync(0xffffffffu, s0, 1);
                s0 += __shfl_xor_sync(0xffffffffu, s0, 2);
                s1 += __shfl_xor_sync(0xffffffffu, s1, 1);
                s1 += __shfl_xor_sync(0xffffffffu, s1, 2);
                if (tig == 0) {
                    const int slot = 8 * (4 * pgrp + rnd) + gid;
                    sredf[nhalf][bi][slot] = make_float2(s0, s1);
                }
            }
        }
        __syncthreads();   // (2) all sredf written

        // ---- per-d reduction: warp w handles batches 2w, 2w+1 ----
        #pragma unroll
        for (int q = 0; q < 2; q++) {
            const int bi = 2 * warp + q;
            float t = 0.0f;
            #pragma unroll
            for (int h = 0; h < 2; h++) {
                const int s = lane + 32 * h;
                const float2 a = sredf[0][bi][s];
                const float2 c = sredf[1][bi][s];
                const float v0 = a.x + c.x + b3v;
                const float v1 = a.y + c.y + b3v;
                t += ((v0 > 0.f) ? v0 : expm1f(v0))
                   + ((v1 > 0.f) ? v1 : expm1f(v1)) + 2.0f;
            }
            t += __shfl_xor_sync(0xffffffffu, t, 16);
            t += __shfl_xor_sync(0xffffffffu, t, 8);
            t += __shfl_xor_sync(0xffffffffu, t, 4);
            t += __shfl_xor_sync(0xffffffffu, t, 2);
            t += __shfl_xor_sync(0xffffffffu, t, 1);
            if (lane == 0) redw[bi] = t;
        }
        __syncthreads();   // (3) redw ready
        if (tid < BPB) hzacc[tid] = fmaf(redw[tid], dszs[tid], hzacc[tid]);
        __syncthreads();   // (4) hzacc/dszs consumed before next-d overwrite
    }

    if (tid < BPB) {
        const int b = b0 + tid;
        if (b < B) out[b] = hzacc[tid];
    }
}

extern "C" void kernel_launch(void* const* d_in, const int* in_sizes, int n_in,
                              void* d_out, int out_size)
{
    const float* z   = (const float*)d_in[0];
    const float* u   = (const float*)d_in[1];
    const float* w01 = (const float*)d_in[2];
    const float* b01 = (const float*)d_in[3];
    const float* w02 = (const float*)d_in[4];
    const float* b02 = (const float*)d_in[5];
    const float* w03 = (const float*)d_in[6];
    const float* b03 = (const float*)d_in[7];
    const float* w11 = (const float*)d_in[8];
    const float* b11 = (const float*)d_in[9];
    const float* w12 = (const float*)d_in[10];
    const float* b12 = (const float*)d_in[11];
    const float* w13 = (const float*)d_in[12];
    const float* b13 = (const float*)d_in[13];
    const float* bias= (const float*)d_in[14];
    float* out = (float*)d_out;

    const int B = in_sizes[0] / 2;
    const int grid = (B + BPB - 1) / BPB;
    mono_mlp_h2f_kernel<<<grid, 128>>>(
        z, u, w01, b01, w02, b02, w03, b03,
        w11, b11, w12, b12, w13, b13, bias, out, B);
}

// round 13
// speedup vs baseline: 1.1088x; 1.1088x over previous
#include <cuda_runtime.h>
#include <cuda_fp16.h>
#include <math.h>

#define HID   64
#define NPT   128
#define LBF   (-5.0f)
#define BPB   16     // batches per block

__device__ __forceinline__ unsigned pack_h2(float lo, float hi) {
    const __half2 h = __floats2half2_rn(lo, hi);
    return *reinterpret_cast<const unsigned*>(&h);
}

// fp16-accumulator mma: C/D are two f16x2 regs
//   c[0] = half2(C[row=gid][2tig], C[row=gid][2tig+1])
//   c[1] = half2(C[row=gid+8][2tig], C[row=gid+8][2tig+1])
__device__ __forceinline__ void mma_f16acc(unsigned c[2],
                                           unsigned a0, unsigned a1, unsigned a2, unsigned a3,
                                           unsigned b0, unsigned b1) {
    asm volatile(
        "mma.sync.aligned.m16n8k16.row.col.f16.f16.f16.f16 "
        "{%0,%1}, {%2,%3,%4,%5}, {%6,%7}, {%0,%1};\n"
        : "+r"(c[0]), "+r"(c[1])
        : "r"(a0), "r"(a1), "r"(a2), "r"(a3), "r"(b0), "r"(b1));
}

// half2 LeakyReLU(0.01): max(h, 0.01*h) elementwise
__device__ __forceinline__ __half2 lrelu2(__half2 h, __half2 c001) {
    return __hmax2(h, __hmul2(h, c001));
}

__global__ __launch_bounds__(128, 8)
void mono_mlp_h2b_kernel(const float* __restrict__ z,  const float* __restrict__ u,
                         const float* __restrict__ w01, const float* __restrict__ b01,
                         const float* __restrict__ w02, const float* __restrict__ b02,
                         const float* __restrict__ w03, const float* __restrict__ b03,
                         const float* __restrict__ w11, const float* __restrict__ b11,
                         const float* __restrict__ w12, const float* __restrict__ b12,
                         const float* __restrict__ w13, const float* __restrict__ b13,
                         const float* __restrict__ bias, float* __restrict__ out, int B)
{
    // B fragments (fp16, m16n8k16 order): bfrag[d*1024 + kt*256 + nt*32 + lane]
    __shared__ uint2  bfrag[2 * 4 * 8 * 32];   // 16 KB (staging for reg hoist)
    // layer-1 packed: w1b1h[d][4*kt + tig]
    __shared__ uint4  w1b1h[2][16];
    // epilogue packed: w3b2h[d][jp] = { h2(w3[2jp], w3[2jp+1]), h2(b2[2jp], b2[2jp+1]) }
    __shared__ uint2  w3b2h[2][32];
    __shared__ float  b3s[2];
    __shared__ unsigned xs2h[BPB][NPT];        // x broadcast as half2 (8 KB)
    __shared__ float  dszs[BPB];
    __shared__ float  sred[2][NPT];            // per-point partials, 2 n-halves
    __shared__ float  hzw[4][BPB];             // per-warp Hz partials

    const int tid = threadIdx.x;

    // ---- Prepack weights (once per block, amortized over 32 batch-tiles) ----
    for (int e = tid; e < 2 * 4 * 8 * 32; e += 128) {
        const int lane = e & 31;
        const int nt   = (e >> 5) & 7;
        const int kt   = (e >> 8) & 3;
        const int d    = (e >> 10) & 1;
        const int n    = 8 * nt + (lane >> 2);
        const int k0   = 16 * kt + 2 * (lane & 3);
        const float* w2 = d ? w12 : w02;
        bfrag[e] = make_uint2(pack_h2(w2[n * 64 + k0],     w2[n * 64 + k0 + 1]),
                              pack_h2(w2[n * 64 + k0 + 8], w2[n * 64 + k0 + 9]));
    }
    if (tid < 32) {
        const int d  = tid >> 4;
        const int j  = tid & 15;           // 4*kt + tig
        const int k0 = 16 * (j >> 2) + 2 * (j & 3);
        const float* w1 = d ? w11 : w01;
        const float* bb = d ? b11 : b01;
        w1b1h[d][j] = make_uint4(pack_h2(w1[k0],     w1[k0 + 1]),
                                 pack_h2(bb[k0],     bb[k0 + 1]),
                                 pack_h2(w1[k0 + 8], w1[k0 + 9]),
                                 pack_h2(bb[k0 + 8], bb[k0 + 9]));
    }
    if (tid < 64) {
        const int d  = tid >> 5;
        const int jp = tid & 31;
        const int j  = 2 * jp;
        const float* w3 = d ? w13 : w03;
        const float* b2 = d ? b12 : b02;
        w3b2h[d][jp] = make_uint2(pack_h2(w3[j], w3[j + 1]),
                                  pack_h2(b2[j], b2[j + 1]));
    }
    if (tid == 0) { b3s[0] = b03[0]; b3s[1] = b13[0]; }
    if (tid < 4 * BPB) hzw[tid >> 4][tid & (BPB - 1)] = 0.0f;

    const int warp  = tid >> 5;
    const int lane  = tid & 31;
    const int gid   = lane >> 2;       // row within m16 group
    const int tig   = lane & 3;        // k / col selector
    const int nhalf = warp & 1;        // n-cols [32*nhalf, +32)
    const int pgrp  = warp >> 1;       // points [64*pgrp, +64)
    const int pbase = 64 * pgrp;
    const int b0    = blockIdx.x * BPB;
    const __half2 c001 = __float2half2_rn(0.01f);
    const __half2 hzero = __float2half2_rn(0.0f);
    __syncthreads();

    #pragma unroll 1
    for (int d = 0; d < 2; d++) {
        // ---- hoist this warp's 16 B-fragments into persistent registers ----
        uint2 bfr[4][4];
        {
            const uint2* bp = &bfrag[d * 1024 + (4 * nhalf) * 32 + lane];
            #pragma unroll
            for (int kt = 0; kt < 4; kt++)
                #pragma unroll
                for (int ntl = 0; ntl < 4; ntl++)
                    bfr[kt][ntl] = bp[kt * 256 + ntl * 32];
        }
        const float b3v = b3s[d];

        // ---- stage 0: layer-0 inputs for all BPB batches of this d ----
        #pragma unroll 1
        for (int it = 0; it < BPB; it++) {
            const int bb_ = b0 + it;
            const float zc  = fmaxf(z[bb_ * 2 + d], LBF);
            const float dsz = (zc - LBF) * (1.0f / (float)(NPT - 1));
            const float uv  = (tid < NPT - 1) ? u[(bb_ * 2 + d) * (NPT - 1) + tid] : 0.0f;
            const float x   = fmaf(dsz, (float)tid + uv, LBF);
            xs2h[it][tid] = pack_h2(x, x);
            if (tid == 0) dszs[it] = dsz;
        }
        __syncthreads();   // (1) xs2h/dszs ready; prior-d stage-3 reads done

        #pragma unroll 1
        for (int bi = 0; bi < BPB; bi++) {
            // ---- stage 2: GEMM, 4 rounds of 16 points x 32 n-cols ----
            #pragma unroll
            for (int rnd = 0; rnd < 4; rnd++) {
                const int pr = pbase + 16 * rnd;
                const int p0 = pr + gid;
                const int p1 = p0 + 8;
                const __half2 x0h = *reinterpret_cast<const __half2*>(&xs2h[bi][p0]);
                const __half2 x1h = *reinterpret_cast<const __half2*>(&xs2h[bi][p1]);

                unsigned acc[4][2];
                #pragma unroll
                for (int ntl = 0; ntl < 4; ntl++) { acc[ntl][0] = 0u; acc[ntl][1] = 0u; }

                #pragma unroll
                for (int kt = 0; kt < 4; kt++) {
                    const uint4 wp = w1b1h[d][4 * kt + tig];
                    const __half2 wlo = *reinterpret_cast<const __half2*>(&wp.x);
                    const __half2 blo = *reinterpret_cast<const __half2*>(&wp.y);
                    const __half2 whi = *reinterpret_cast<const __half2*>(&wp.z);
                    const __half2 bhi = *reinterpret_cast<const __half2*>(&wp.w);

                    const __half2 h0lo = lrelu2(__hfma2(x0h, wlo, blo), c001);
                    const __half2 h1lo = lrelu2(__hfma2(x1h, wlo, blo), c001);
                    const __half2 h0hi = lrelu2(__hfma2(x0h, whi, bhi), c001);
                    const __half2 h1hi = lrelu2(__hfma2(x1h, whi, bhi), c001);
                    const unsigned a0 = *reinterpret_cast<const unsigned*>(&h0lo);
                    const unsigned a1 = *reinterpret_cast<const unsigned*>(&h1lo);
                    const unsigned a2 = *reinterpret_cast<const unsigned*>(&h0hi);
                    const unsigned a3 = *reinterpret_cast<const unsigned*>(&h1hi);

                    mma_f16acc(acc[0], a0, a1, a2, a3, bfr[kt][0].x, bfr[kt][0].y);
                    mma_f16acc(acc[1], a0, a1, a2, a3, bfr[kt][1].x, bfr[kt][1].y);
                    mma_f16acc(acc[2], a0, a1, a2, a3, bfr[kt][2].x, bfr[kt][2].y);
                    mma_f16acc(acc[3], a0, a1, a2, a3, bfr[kt][3].x, bfr[kt][3].y);
                }

                // ---- epilogue (half2 dot, fp32 parallel folds) ----
                __half2 s0h = hzero, s1h = hzero;
                #pragma unroll
                for (int ntl = 0; ntl < 4; ntl++) {
                    const uint2 wb = w3b2h[d][16 * nhalf + 4 * ntl + tig];
                    const __half2 w3p = *reinterpret_cast<const __half2*>(&wb.x);
                    const __half2 b2p = *reinterpret_cast<const __half2*>(&wb.y);
                    const __half2 p0p = *reinterpret_cast<const __half2*>(&acc[ntl][0]);
                    const __half2 p1p = *reinterpret_cast<const __half2*>(&acc[ntl][1]);
                    s0h = __hfma2(lrelu2(__hadd2(p0p, b2p), c001), w3p, s0h);
                    s1h = __hfma2(lrelu2(__hadd2(p1p, b2p), c001), w3p, s1h);
                }
                float s0 = __low2float(s0h) + __high2float(s0h);
                float s1 = __low2float(s1h) + __high2float(s1h);
                s0 += __shfl_xor_sync(0xffffffffu, s0, 1);
                s0 += __shfl_xor_sync(0xffffffffu, s0, 2);
                s1 += __shfl_xor_sync(0xffffffffu, s1, 1);
                s1 += __shfl_xor_sync(0xffffffffu, s1, 2);
                if (tig == 0) {
                    sred[nhalf][p0] = s0;
                    sred[nhalf][p1] = s1;
                }
            }
            __syncthreads();   // (B) sred complete

            // ---- stage 3: combine n-halves, ELU(+1)=exp, warp-accumulate ----
            {
                const float v = sred[0][tid] + sred[1][tid] + b3v;
                // elu(v) + 1 == v > 0 ? v + 1 : exp(v)   (exact identity)
                float t = (v > 0.f) ? (v + 1.0f) : __expf(v);
                t += __shfl_xor_sync(0xffffffffu, t, 16);
                t += __shfl_xor_sync(0xffffffffu, t, 8);
                t += __shfl_xor_sync(0xffffffffu, t, 4);
                t += __shfl_xor_sync(0xffffffffu, t, 2);
                t += __shfl_xor_sync(0xffffffffu, t, 1);
                if (lane == 0) hzw[warp][bi] = fmaf(t, dszs[bi], hzw[warp][bi]);
            }
            __syncthreads();   // (C) stage-3 reads done; sred safe for next batch
        }
    }

    if (tid < BPB) {
        const int b = b0 + tid;
        if (b < B)
            out[b] = bias[0] + hzw[0][tid] + hzw[1][tid] + hzw[2][tid] + hzw[3][tid];
    }
}

extern "C" void kernel_launch(void* const* d_in, const int* in_sizes, int n_in,
                              void* d_out, int out_size)
{
    const float* z   = (const float*)d_in[0];
    const float* u   = (const float*)d_in[1];
    const float* w01 = (const float*)d_in[2];
    const float* b01 = (const float*)d_in[3];
    const float* w02 = (const float*)d_in[4];
    const float* b02 = (const float*)d_in[5];
    const float* w03 = (const float*)d_in[6];
    const float* b03 = (const float*)d_in[7];
    const float* w11 = (const float*)d_in[8];
    const float* b11 = (const float*)d_in[9];
    const float* w12 = (const float*)d_in[10];
    const float* b12 = (const float*)d_in[11];
    const float* w13 = (const float*)d_in[12];
    const float* b13 = (const float*)d_in[13];
    const float* bias= (const float*)d_in[14];
    float* out = (float*)d_out;

    const int B = in_sizes[0] / 2;
    const int grid = (B + BPB - 1) / BPB;
    mono_mlp_h2b_kernel<<<grid, 128>>>(
        z, u, w01, b01, w02, b02, w03, b03,
        w11, b11, w12, b12, w13, b13, bias, out, B);
}

// round 14
// speedup vs baseline: 1.1688x; 1.0541x over previous
#include <cuda_runtime.h>
#include <cuda_fp16.h>
#include <math.h>

#define HID   64
#define NPT   128
#define LBF   (-5.0f)
#define BPB   8      // batches per block

__device__ __forceinline__ unsigned pack_h2(float lo, float hi) {
    const __half2 h = __floats2half2_rn(lo, hi);
    return *reinterpret_cast<const unsigned*>(&h);
}

// fp16-accumulator mma: C/D are two f16x2 regs
//   c[0] = half2(C[row=gid][2tig], C[row=gid][2tig+1])
//   c[1] = half2(C[row=gid+8][2tig], C[row=gid+8][2tig+1])
__device__ __forceinline__ void mma_f16acc(unsigned c[2],
                                           unsigned a0, unsigned a1, unsigned a2, unsigned a3,
                                           unsigned b0, unsigned b1) {
    asm volatile(
        "mma.sync.aligned.m16n8k16.row.col.f16.f16.f16.f16 "
        "{%0,%1}, {%2,%3,%4,%5}, {%6,%7}, {%0,%1};\n"
        : "+r"(c[0]), "+r"(c[1])
        : "r"(a0), "r"(a1), "r"(a2), "r"(a3), "r"(b0), "r"(b1));
}

// half2 LeakyReLU(0.01): max(h, 0.01*h) elementwise
__device__ __forceinline__ __half2 lrelu2(__half2 h, __half2 c001) {
    return __hmax2(h, __hmul2(h, c001));
}

__global__ __launch_bounds__(128, 8)
void mono_mlp_h2c_kernel(const float* __restrict__ z,  const float* __restrict__ u,
                         const float* __restrict__ w01, const float* __restrict__ b01,
                         const float* __restrict__ w02, const float* __restrict__ b02,
                         const float* __restrict__ w03, const float* __restrict__ b03,
                         const float* __restrict__ w11, const float* __restrict__ b11,
                         const float* __restrict__ w12, const float* __restrict__ b12,
                         const float* __restrict__ w13, const float* __restrict__ b13,
                         const float* __restrict__ bias, float* __restrict__ out, int B)
{
    // B fragments (fp16, m16n8k16 order): bfrag[d*1024 + kt*256 + nt*32 + lane]
    __shared__ uint2  bfrag[2 * 4 * 8 * 32];   // 16 KB (staging for reg hoist)
    // layer-1 packed: w1b1h[d][4*kt + tig]
    __shared__ uint4  w1b1h[2][16];
    // epilogue packed: w3b2h[d][jp] = { h2(w3[2jp], w3[2jp+1]), h2(b2[2jp], b2[2jp+1]) }
    __shared__ uint2  w3b2h[2][32];
    __shared__ float  b3s[2];
    __shared__ unsigned xs2h[BPB][NPT];        // x broadcast as half2 (4 KB)
    __shared__ float  dszs[BPB];
    __shared__ float  sred[2][2][NPT];         // [bi&1][nhalf][p] double-buffered
    __shared__ float  hzw[4][BPB];             // per-warp Hz partials

    const int tid = threadIdx.x;

    // ---- Prepack weights (once per block) ----
    for (int e = tid; e < 2 * 4 * 8 * 32; e += 128) {
        const int lane = e & 31;
        const int nt   = (e >> 5) & 7;
        const int kt   = (e >> 8) & 3;
        const int d    = (e >> 10) & 1;
        const int n    = 8 * nt + (lane >> 2);
        const int k0   = 16 * kt + 2 * (lane & 3);
        const float* w2 = d ? w12 : w02;
        bfrag[e] = make_uint2(pack_h2(w2[n * 64 + k0],     w2[n * 64 + k0 + 1]),
                              pack_h2(w2[n * 64 + k0 + 8], w2[n * 64 + k0 + 9]));
    }
    if (tid < 32) {
        const int d  = tid >> 4;
        const int j  = tid & 15;           // 4*kt + tig
        const int k0 = 16 * (j >> 2) + 2 * (j & 3);
        const float* w1 = d ? w11 : w01;
        const float* bb = d ? b11 : b01;
        w1b1h[d][j] = make_uint4(pack_h2(w1[k0],     w1[k0 + 1]),
                                 pack_h2(bb[k0],     bb[k0 + 1]),
                                 pack_h2(w1[k0 + 8], w1[k0 + 9]),
                                 pack_h2(bb[k0 + 8], bb[k0 + 9]));
    }
    if (tid < 64) {
        const int d  = tid >> 5;
        const int jp = tid & 31;
        const int j  = 2 * jp;
        const float* w3 = d ? w13 : w03;
        const float* b2 = d ? b12 : b02;
        w3b2h[d][jp] = make_uint2(pack_h2(w3[j], w3[j + 1]),
                                  pack_h2(b2[j], b2[j + 1]));
    }
    if (tid == 0) { b3s[0] = b03[0]; b3s[1] = b13[0]; }
    if (tid < 4 * BPB) hzw[tid >> 3][tid & (BPB - 1)] = 0.0f;

    const int warp  = tid >> 5;
    const int lane  = tid & 31;
    const int gid   = lane >> 2;       // row within m16 group
    const int tig   = lane & 3;        // k / col selector
    const int nhalf = warp & 1;        // n-cols [32*nhalf, +32)
    const int pgrp  = warp >> 1;       // points [64*pgrp, +64)
    const int pbase = 64 * pgrp;
    const int b0    = blockIdx.x * BPB;
    const __half2 c001 = __float2half2_rn(0.01f);
    const __half2 hzero = __float2half2_rn(0.0f);
    __syncthreads();

    #pragma unroll 1
    for (int d = 0; d < 2; d++) {
        // ---- hoist this warp's 16 B-fragments into persistent registers ----
        uint2 bfr[4][4];
        {
            const uint2* bp = &bfrag[d * 1024 + (4 * nhalf) * 32 + lane];
            #pragma unroll
            for (int kt = 0; kt < 4; kt++)
                #pragma unroll
                for (int ntl = 0; ntl < 4; ntl++)
                    bfr[kt][ntl] = bp[kt * 256 + ntl * 32];
        }
        const float b3v = b3s[d];

        __syncthreads();   // (0) prior-d stage2/3 fully done before xs2h rewrite

        // ---- stage 0: layer-0 inputs for all BPB batches of this d ----
        #pragma unroll 1
        for (int it = 0; it < BPB; it++) {
            const int bb_ = b0 + it;
            const float zc  = fmaxf(z[bb_ * 2 + d], LBF);
            const float dsz = (zc - LBF) * (1.0f / (float)(NPT - 1));
            const float uv  = (tid < NPT - 1) ? u[(bb_ * 2 + d) * (NPT - 1) + tid] : 0.0f;
            const float x   = fmaf(dsz, (float)tid + uv, LBF);
            xs2h[it][tid] = pack_h2(x, x);
            if (tid == 0) dszs[it] = dsz;
        }
        __syncthreads();   // (1) xs2h/dszs ready

        #pragma unroll 1
        for (int bi = 0; bi < BPB; bi++) {
            float* sbuf0 = sred[bi & 1][0];
            float* sbuf1 = sred[bi & 1][1];
            float* sw    = (nhalf == 0) ? sbuf0 : sbuf1;

            // ---- stage 2: GEMM, 4 rounds of 16 points x 32 n-cols ----
            #pragma unroll
            for (int rnd = 0; rnd < 4; rnd++) {
                const int pr = pbase + 16 * rnd;
                const int p0 = pr + gid;
                const int p1 = p0 + 8;
                const __half2 x0h = *reinterpret_cast<const __half2*>(&xs2h[bi][p0]);
                const __half2 x1h = *reinterpret_cast<const __half2*>(&xs2h[bi][p1]);

                unsigned acc[4][2];
                #pragma unroll
                for (int ntl = 0; ntl < 4; ntl++) { acc[ntl][0] = 0u; acc[ntl][1] = 0u; }

                #pragma unroll
                for (int kt = 0; kt < 4; kt++) {
                    const uint4 wp = w1b1h[d][4 * kt + tig];
                    const __half2 wlo = *reinterpret_cast<const __half2*>(&wp.x);
                    const __half2 blo = *reinterpret_cast<const __half2*>(&wp.y);
                    const __half2 whi = *reinterpret_cast<const __half2*>(&wp.z);
                    const __half2 bhi = *reinterpret_cast<const __half2*>(&wp.w);

                    const __half2 h0lo = lrelu2(__hfma2(x0h, wlo, blo), c001);
                    const __half2 h1lo = lrelu2(__hfma2(x1h, wlo, blo), c001);
                    const __half2 h0hi = lrelu2(__hfma2(x0h, whi, bhi), c001);
                    const __half2 h1hi = lrelu2(__hfma2(x1h, whi, bhi), c001);
                    const unsigned a0 = *reinterpret_cast<const unsigned*>(&h0lo);
                    const unsigned a1 = *reinterpret_cast<const unsigned*>(&h1lo);
                    const unsigned a2 = *reinterpret_cast<const unsigned*>(&h0hi);
                    const unsigned a3 = *reinterpret_cast<const unsigned*>(&h1hi);

                    mma_f16acc(acc[0], a0, a1, a2, a3, bfr[kt][0].x, bfr[kt][0].y);
                    mma_f16acc(acc[1], a0, a1, a2, a3, bfr[kt][1].x, bfr[kt][1].y);
                    mma_f16acc(acc[2], a0, a1, a2, a3, bfr[kt][2].x, bfr[kt][2].y);
                    mma_f16acc(acc[3], a0, a1, a2, a3, bfr[kt][3].x, bfr[kt][3].y);
                }

                // ---- epilogue (half2 dot, fp32 parallel folds) ----
                __half2 s0h = hzero, s1h = hzero;
                #pragma unroll
                for (int ntl = 0; ntl < 4; ntl++) {
                    const uint2 wbv = w3b2h[d][16 * nhalf + 4 * ntl + tig];
                    const __half2 w3p = *reinterpret_cast<const __half2*>(&wbv.x);
                    const __half2 b2p = *reinterpret_cast<const __half2*>(&wbv.y);
                    const __half2 p0p = *reinterpret_cast<const __half2*>(&acc[ntl][0]);
                    const __half2 p1p = *reinterpret_cast<const __half2*>(&acc[ntl][1]);
                    s0h = __hfma2(lrelu2(__hadd2(p0p, b2p), c001), w3p, s0h);
                    s1h = __hfma2(lrelu2(__hadd2(p1p, b2p), c001), w3p, s1h);
                }
                float s0 = __low2float(s0h) + __high2float(s0h);
                float s1 = __low2float(s1h) + __high2float(s1h);
                s0 += __shfl_xor_sync(0xffffffffu, s0, 1);
                s0 += __shfl_xor_sync(0xffffffffu, s0, 2);
                s1 += __shfl_xor_sync(0xffffffffu, s1, 1);
                s1 += __shfl_xor_sync(0xffffffffu, s1, 2);
                if (tig == 0) {
                    sw[p0] = s0;
                    sw[p1] = s1;
                }
            }
            __syncthreads();   // (B) this batch's sred buffer complete

            // ---- stage 3: combine n-halves, ELU(+1)=exp, warp-accumulate ----
            // Next batch writes the OTHER sred buffer; barrier (B of bi+1)
            // transitively orders these reads before the bi+2 rewrite.
            {
                const float v = sbuf0[tid] + sbuf1[tid] + b3v;
                float t = (v > 0.f) ? (v + 1.0f) : __expf(v);   // elu(v)+1
                t += __shfl_xor_sync(0xffffffffu, t, 16);
                t += __shfl_xor_sync(0xffffffffu, t, 8);
                t += __shfl_xor_sync(0xffffffffu, t, 4);
                t += __shfl_xor_sync(0xffffffffu, t, 2);
                t += __shfl_xor_sync(0xffffffffu, t, 1);
                if (lane == 0) hzw[warp][bi] = fmaf(t, dszs[bi], hzw[warp][bi]);
            }
        }
    }

    __syncthreads();
    if (tid < BPB) {
        const int b = b0 + tid;
        if (b < B)
            out[b] = bias[0] + hzw[0][tid] + hzw[1][tid] + hzw[2][tid] + hzw[3][tid];
    }
}

extern "C" void kernel_launch(void* const* d_in, const int* in_sizes, int n_in,
                              void* d_out, int out_size)
{
    const float* z   = (const float*)d_in[0];
    const float* u   = (const float*)d_in[1];
    const float* w01 = (const float*)d_in[2];
    const float* b01 = (const float*)d_in[3];
    const float* w02 = (const float*)d_in[4];
    const float* b02 = (const float*)d_in[5];
    const float* w03 = (const float*)d_in[6];
    const float* b03 = (const float*)d_in[7];
    const float* w11 = (const float*)d_in[8];
    const float* b11 = (const float*)d_in[9];
    const float* w12 = (const float*)d_in[10];
    const float* b12 = (const float*)d_in[11];
    const float* w13 = (const float*)d_in[12];
    const float* b13 = (const float*)d_in[13];
    const float* bias= (const float*)d_in[14];
    float* out = (float*)d_out;

    const int B = in_sizes[0] / 2;
    const int grid = (B + BPB - 1) / BPB;
    mono_mlp_h2c_kernel<<<grid, 128>>>(
        z, u, w01, b01, w02, b02, w03, b03,
        w11, b11, w12, b12, w13, b13, bias, out, B);
}